// round 2
// baseline (speedup 1.0000x reference)
#include <cuda_runtime.h>
#include <cstdint>
#include <cstddef>

#define S_LEN 512
#define BATCH 64
#define HID   1024
#define NG    4096            // 4*HID, gate vector width
#define MTOT  (S_LEN*BATCH)   // 32768

// ---- scratch (device globals; no runtime allocation) ----
__device__ float g_gx[(size_t)MTOT * NG];   // precomputed x@W_ih^T + b  (536MB)
__device__ float g_h[2][BATCH * HID];       // double-buffered hidden state
__device__ float g_c[BATCH * HID];          // cell state
__device__ float g_b[NG];                   // b_ih + b_hh
__device__ float g_wsum[(size_t)NG * HID];  // W_ih + W_hh (for autoregressive steps)

// ---- tf32 helpers ----
__device__ __forceinline__ float tfr(float f) {
    unsigned u;
    asm("cvt.rna.tf32.f32 %0, %1;" : "=r"(u) : "f"(f));
    return __uint_as_float(u);
}

__device__ __forceinline__ void mma_tf32(float c[4], const unsigned a[4], const unsigned b[2]) {
    asm volatile(
        "mma.sync.aligned.m16n8k8.row.col.f32.tf32.tf32.f32 "
        "{%0,%1,%2,%3}, {%4,%5,%6,%7}, {%8,%9}, {%0,%1,%2,%3};\n"
        : "+f"(c[0]), "+f"(c[1]), "+f"(c[2]), "+f"(c[3])
        : "r"(a[0]), "r"(a[1]), "r"(a[2]), "r"(a[3]), "r"(b[0]), "r"(b[1]));
}

// ============================================================================
// prep: b = b_ih + b_hh ; Wsum = W_ih + W_hh ; h0, c0 init
// ============================================================================
__global__ void prep_kernel(const float* __restrict__ W_ih, const float* __restrict__ W_hh,
                            const float* __restrict__ b_ih, const float* __restrict__ b_hh,
                            const float* __restrict__ hx0,  const float* __restrict__ cx0) {
    int idx = blockIdx.x * blockDim.x + threadIdx.x;
    if (idx < NG * HID) g_wsum[idx] = W_ih[idx] + W_hh[idx];
    if (idx < NG)       g_b[idx]    = b_ih[idx] + b_hh[idx];
    if (idx < BATCH * HID) {
        g_h[0][idx] = hx0[idx];
        g_c[idx]    = cx0[idx];
    }
}

// ============================================================================
// gemmA: g_gx[M=32768, NG=4096] = X[M,1024] @ W_ih^T + b   (tf32 MMA)
// CTA tile 128x64, 8 warps (4M x 2N), warp tile 32x32, K-chunk 32.
// ============================================================================
__global__ __launch_bounds__(256) void gemmA_kernel(const float* __restrict__ X,
                                                    const float* __restrict__ W) {
    __shared__ float As[128][36];
    __shared__ float Bs[64][36];

    const int tid  = threadIdx.x;
    const int wid  = tid >> 5, lane = tid & 31;
    const int wm   = wid >> 1;      // 0..3
    const int wn   = wid & 1;       // 0..1
    const int m0   = blockIdx.y * 128;
    const int n0   = blockIdx.x * 64;

    const float* Ag = X + (size_t)m0 * HID;
    const float* Bg = W + (size_t)n0 * HID;

    float c[2][4][4];
    #pragma unroll
    for (int mt = 0; mt < 2; mt++)
        #pragma unroll
        for (int nt = 0; nt < 4; nt++)
            #pragma unroll
            for (int r = 0; r < 4; r++) c[mt][nt][r] = 0.f;

    float4 ra[4], rb[2];
    auto loadG = [&](int kc) {
        const int k0 = kc * 32;
        #pragma unroll
        for (int i = 0; i < 4; i++) {
            int l = tid + i * 256;         // 0..1023
            int r = l >> 3, f = l & 7;     // r: 0..127
            ra[i] = *reinterpret_cast<const float4*>(Ag + (size_t)r * HID + k0 + f * 4);
        }
        #pragma unroll
        for (int i = 0; i < 2; i++) {
            int l = tid + i * 256;         // 0..511
            int r = l >> 3, f = l & 7;     // r: 0..63
            rb[i] = *reinterpret_cast<const float4*>(Bg + (size_t)r * HID + k0 + f * 4);
        }
    };

    loadG(0);
    for (int kc = 0; kc < 32; kc++) {
        #pragma unroll
        for (int i = 0; i < 4; i++) {
            int l = tid + i * 256;
            int r = l >> 3, f = l & 7;
            float4 v = ra[i];
            v.x = tfr(v.x); v.y = tfr(v.y); v.z = tfr(v.z); v.w = tfr(v.w);
            *reinterpret_cast<float4*>(&As[r][f * 4]) = v;
        }
        #pragma unroll
        for (int i = 0; i < 2; i++) {
            int l = tid + i * 256;
            int r = l >> 3, f = l & 7;
            float4 v = rb[i];
            v.x = tfr(v.x); v.y = tfr(v.y); v.z = tfr(v.z); v.w = tfr(v.w);
            *reinterpret_cast<float4*>(&Bs[r][f * 4]) = v;
        }
        __syncthreads();
        if (kc + 1 < 32) loadG(kc + 1);

        #pragma unroll
        for (int kk = 0; kk < 4; kk++) {
            const int k8 = kk * 8;
            unsigned a[2][4], b[4][2];
            #pragma unroll
            for (int mt = 0; mt < 2; mt++) {
                int r0 = wm * 32 + mt * 16 + (lane >> 2);
                a[mt][0] = __float_as_uint(As[r0][k8 + (lane & 3)]);
                a[mt][1] = __float_as_uint(As[r0 + 8][k8 + (lane & 3)]);
                a[mt][2] = __float_as_uint(As[r0][k8 + (lane & 3) + 4]);
                a[mt][3] = __float_as_uint(As[r0 + 8][k8 + (lane & 3) + 4]);
            }
            #pragma unroll
            for (int nt = 0; nt < 4; nt++) {
                int rn = wn * 32 + nt * 8 + (lane >> 2);
                b[nt][0] = __float_as_uint(Bs[rn][k8 + (lane & 3)]);
                b[nt][1] = __float_as_uint(Bs[rn][k8 + (lane & 3) + 4]);
            }
            #pragma unroll
            for (int mt = 0; mt < 2; mt++)
                #pragma unroll
                for (int nt = 0; nt < 4; nt++)
                    mma_tf32(c[mt][nt], a[mt], b[nt]);
        }
        __syncthreads();
    }

    // epilogue: + bias, write g_gx
    #pragma unroll
    for (int mt = 0; mt < 2; mt++) {
        #pragma unroll
        for (int nt = 0; nt < 4; nt++) {
            int row = m0 + wm * 32 + mt * 16 + (lane >> 2);
            int col = n0 + wn * 32 + nt * 8 + 2 * (lane & 3);
            float b0 = g_b[col], b1 = g_b[col + 1];
            g_gx[(size_t)row * NG + col]           = c[mt][nt][0] + b0;
            g_gx[(size_t)row * NG + col + 1]       = c[mt][nt][1] + b1;
            g_gx[(size_t)(row + 8) * NG + col]     = c[mt][nt][2] + b0;
            g_gx[(size_t)(row + 8) * NG + col + 1] = c[mt][nt][3] + b1;
        }
    }
}

// ============================================================================
// step: one LSTM time step, fused GEMM + elementwise.
// 128 CTAs; CTA jb owns h-columns j0..j0+7 and the 32 gate columns
// {g*1024 + j0 + jj}. 8 warps = 2(M) x 4(gate). Warp tile 32(M) x 8(N).
// AR=false: gates = g_gx[t] + h @ W_hh^T     (bias already inside g_gx)
// AR=true : gates = g_b    + h @ Wsum^T ; also writes h to out_slot.
// ============================================================================
template <bool AR>
__global__ __launch_bounds__(256) void step_kernel(int t,
                                                   const float* __restrict__ Whh,
                                                   float* __restrict__ out_slot) {
    __shared__ float sm[64 * 36 + 32 * 36];   // As[64][36] | Bs[32][36]
    float (*As)[36] = reinterpret_cast<float(*)[36]>(sm);
    float (*Bs)[36] = reinterpret_cast<float(*)[36]>(sm + 64 * 36);

    const int tid = threadIdx.x, wid = tid >> 5, lane = tid & 31;
    const int wn = wid & 3;      // gate index
    const int wm = wid >> 2;     // 0..1
    const int j0 = blockIdx.x * 8;

    const float* __restrict__ h_in  = g_h[t & 1];
    float*       __restrict__ h_out = g_h[(t + 1) & 1];
    const float* __restrict__ W     = AR ? g_wsum : Whh;
    const float* __restrict__ gx_t  = g_gx + (size_t)t * BATCH * NG;

    // accumulator init (bias or precomputed input projection)
    float c[2][4];
    #pragma unroll
    for (int mt = 0; mt < 2; mt++) {
        int row = wm * 32 + mt * 16 + (lane >> 2);
        int jj  = 2 * (lane & 3);
        int n   = wn * HID + j0 + jj;
        if (AR) {
            float b0 = g_b[n], b1 = g_b[n + 1];
            c[mt][0] = b0; c[mt][1] = b1;
            c[mt][2] = b0; c[mt][3] = b1;
        } else {
            c[mt][0] = gx_t[(size_t)row * NG + n];
            c[mt][1] = gx_t[(size_t)row * NG + n + 1];
            c[mt][2] = gx_t[(size_t)(row + 8) * NG + n];
            c[mt][3] = gx_t[(size_t)(row + 8) * NG + n + 1];
        }
    }

    float4 ra[2], rb;
    auto loadG = [&](int kc) {
        const int k0 = kc * 32;
        #pragma unroll
        for (int i = 0; i < 2; i++) {
            int l = tid + i * 256;        // 0..511
            int r = l >> 3, f = l & 7;    // r: 0..63
            ra[i] = *reinterpret_cast<const float4*>(h_in + (size_t)r * HID + k0 + f * 4);
        }
        {
            int r = tid >> 3, f = tid & 7;   // r: 0..31
            int gate = r >> 3, jj2 = r & 7;
            rb = *reinterpret_cast<const float4*>(
                W + (size_t)(gate * HID + j0 + jj2) * HID + k0 + f * 4);
        }
    };

    loadG(0);
    for (int kc = 0; kc < 32; kc++) {
        #pragma unroll
        for (int i = 0; i < 2; i++) {
            int l = tid + i * 256;
            int r = l >> 3, f = l & 7;
            float4 va = ra[i];
            va.x = tfr(va.x); va.y = tfr(va.y); va.z = tfr(va.z); va.w = tfr(va.w);
            *reinterpret_cast<float4*>(&As[r][f * 4]) = va;
        }
        {
            int r = tid >> 3, f = tid & 7;
            float4 vb = rb;
            vb.x = tfr(vb.x); vb.y = tfr(vb.y); vb.z = tfr(vb.z); vb.w = tfr(vb.w);
            *reinterpret_cast<float4*>(&Bs[r][f * 4]) = vb;
        }
        __syncthreads();
        if (kc + 1 < 32) loadG(kc + 1);

        #pragma unroll
        for (int kk = 0; kk < 4; kk++) {
            const int k8 = kk * 8;
            unsigned a[2][4], b[2];
            #pragma unroll
            for (int mt = 0; mt < 2; mt++) {
                int r0 = wm * 32 + mt * 16 + (lane >> 2);
                a[mt][0] = __float_as_uint(As[r0][k8 + (lane & 3)]);
                a[mt][1] = __float_as_uint(As[r0 + 8][k8 + (lane & 3)]);
                a[mt][2] = __float_as_uint(As[r0][k8 + (lane & 3) + 4]);
                a[mt][3] = __float_as_uint(As[r0 + 8][k8 + (lane & 3) + 4]);
            }
            {
                int rn = wn * 8 + (lane >> 2);
                b[0] = __float_as_uint(Bs[rn][k8 + (lane & 3)]);
                b[1] = __float_as_uint(Bs[rn][k8 + (lane & 3) + 4]);
            }
            #pragma unroll
            for (int mt = 0; mt < 2; mt++)
                mma_tf32(c[mt], a[mt], b);
        }
        __syncthreads();
    }

    // gate exchange through SMEM: sg[(gate*64+m)*9 + jj]  (pad 9 vs 8 for banks)
    float* sg = sm;   // 4*64*9 = 2304 floats, fits
    #pragma unroll
    for (int mt = 0; mt < 2; mt++) {
        int row = wm * 32 + mt * 16 + (lane >> 2);
        int jj  = 2 * (lane & 3);
        sg[(wn * 64 + row) * 9 + jj]         = c[mt][0];
        sg[(wn * 64 + row) * 9 + jj + 1]     = c[mt][1];
        sg[(wn * 64 + row + 8) * 9 + jj]     = c[mt][2];
        sg[(wn * 64 + row + 8) * 9 + jj + 1] = c[mt][3];
    }
    __syncthreads();

    // elementwise LSTM cell update for this CTA's 64x8 slice
    for (int q = tid; q < BATCH * 8; q += 256) {
        int m = q >> 3, jj = q & 7;
        float gi = sg[(0 * 64 + m) * 9 + jj];
        float gf = sg[(1 * 64 + m) * 9 + jj];
        float gg = sg[(2 * 64 + m) * 9 + jj];
        float go = sg[(3 * 64 + m) * 9 + jj];
        int cidx = m * HID + j0 + jj;
        float cold = g_c[cidx];
        float si = 1.f / (1.f + expf(-gi));
        float sf = 1.f / (1.f + expf(-gf));
        float so = 1.f / (1.f + expf(-go));
        float cn = sf * cold + si * tanhf(gg);
        float hn = so * tanhf(cn);
        g_c[cidx]   = cn;
        h_out[cidx] = hn;
        if (AR) out_slot[cidx] = hn;
    }
}

// ============================================================================
// launch
// ============================================================================
extern "C" void kernel_launch(void* const* d_in, const int* in_sizes, int n_in,
                              void* d_out, int out_size) {
    (void)in_sizes; (void)n_in; (void)out_size;
    const float* x    = (const float*)d_in[0];
    const float* hx0  = (const float*)d_in[1];
    const float* cx0  = (const float*)d_in[2];
    const float* W_ih = (const float*)d_in[3];
    const float* W_hh = (const float*)d_in[4];
    const float* b_ih = (const float*)d_in[5];
    const float* b_hh = (const float*)d_in[6];
    float* out = (float*)d_out;

    // 1. prep: biases, Wsum, state init
    prep_kernel<<<(NG * HID + 255) / 256, 256>>>(W_ih, W_hh, b_ih, b_hh, hx0, cx0);

    // 2. precompute input projections for all 512 steps
    dim3 gA(NG / 64, MTOT / 128);
    gemmA_kernel<<<gA, 256>>>(x, W_ih);

    // 3. 512 recurrent steps
    for (int t = 0; t < S_LEN; t++)
        step_kernel<false><<<HID / 8, 256>>>(t, W_hh, nullptr);

    // 4. two autoregressive steps; write h to output
    for (int t = S_LEN; t < S_LEN + 2; t++)
        step_kernel<true><<<HID / 8, 256>>>(t, nullptr,
                                            out + (size_t)(t - S_LEN) * BATCH * HID);
}

// round 3
// speedup vs baseline: 1.3071x; 1.3071x over previous
#include <cuda_runtime.h>
#include <cstdint>
#include <cstddef>

#define S_LEN 512
#define BATCH 64
#define HID   1024
#define NG    4096            // 4*HID
#define MTOT  (S_LEN*BATCH)   // 32768
#define GRID  128             // persistent CTAs (HID/8)
#define WSTR  1028            // Ws row stride (floats): %32==4 -> conflict-free b-frags

// ---- scratch (device globals; no runtime allocation) ----
__device__ float g_gx[(size_t)MTOT * NG];   // precomputed x@W_ih^T + b
__device__ float g_h[2][BATCH * HID];       // double-buffered hidden state
__device__ float g_c[BATCH * HID];          // cell state
__device__ float g_b[NG];                   // b_ih + b_hh
__device__ float g_wsum[(size_t)NG * HID];  // W_ih + W_hh (AR steps)
__device__ unsigned g_bar;                  // grid barrier counter

// ---- tf32 helpers ----
__device__ __forceinline__ float tfr(float f) {
    unsigned u;
    asm("cvt.rna.tf32.f32 %0, %1;" : "=r"(u) : "f"(f));
    return __uint_as_float(u);
}

__device__ __forceinline__ void mma_tf32(float c[4], const unsigned a[4], const unsigned b[2]) {
    asm volatile(
        "mma.sync.aligned.m16n8k8.row.col.f32.tf32.tf32.f32 "
        "{%0,%1,%2,%3}, {%4,%5,%6,%7}, {%8,%9}, {%0,%1,%2,%3};\n"
        : "+f"(c[0]), "+f"(c[1]), "+f"(c[2]), "+f"(c[3])
        : "r"(a[0]), "r"(a[1]), "r"(a[2]), "r"(a[3]), "r"(b[0]), "r"(b[1]));
}

// ============================================================================
// prep: b = b_ih + b_hh ; Wsum = W_ih + W_hh ; h0, c0 init ; reset barrier
// ============================================================================
__global__ void prep_kernel(const float* __restrict__ W_ih, const float* __restrict__ W_hh,
                            const float* __restrict__ b_ih, const float* __restrict__ b_hh,
                            const float* __restrict__ hx0,  const float* __restrict__ cx0) {
    int idx = blockIdx.x * blockDim.x + threadIdx.x;
    if (idx == 0) g_bar = 0;
    if (idx < NG * HID) g_wsum[idx] = W_ih[idx] + W_hh[idx];
    if (idx < NG)       g_b[idx]    = b_ih[idx] + b_hh[idx];
    if (idx < BATCH * HID) {
        g_h[0][idx] = hx0[idx];
        g_c[idx]    = cx0[idx];
    }
}

// ============================================================================
// gemmA: g_gx[M=32768, NG=4096] = X[M,1024] @ W_ih^T + b   (tf32 MMA)
// CTA tile 128x64, 8 warps (4M x 2N), warp tile 32x32, K-chunk 32.
// ============================================================================
__global__ __launch_bounds__(256) void gemmA_kernel(const float* __restrict__ X,
                                                    const float* __restrict__ W) {
    __shared__ float As[128][36];
    __shared__ float Bs[64][36];

    const int tid  = threadIdx.x;
    const int wid  = tid >> 5, lane = tid & 31;
    const int wm   = wid >> 1;
    const int wn   = wid & 1;
    const int m0   = blockIdx.y * 128;
    const int n0   = blockIdx.x * 64;

    const float* Ag = X + (size_t)m0 * HID;
    const float* Bg = W + (size_t)n0 * HID;

    float c[2][4][4];
    #pragma unroll
    for (int mt = 0; mt < 2; mt++)
        #pragma unroll
        for (int nt = 0; nt < 4; nt++)
            #pragma unroll
            for (int r = 0; r < 4; r++) c[mt][nt][r] = 0.f;

    float4 ra[4], rb[2];
    auto loadG = [&](int kc) {
        const int k0 = kc * 32;
        #pragma unroll
        for (int i = 0; i < 4; i++) {
            int l = tid + i * 256;
            int r = l >> 3, f = l & 7;
            ra[i] = *reinterpret_cast<const float4*>(Ag + (size_t)r * HID + k0 + f * 4);
        }
        #pragma unroll
        for (int i = 0; i < 2; i++) {
            int l = tid + i * 256;
            int r = l >> 3, f = l & 7;
            rb[i] = *reinterpret_cast<const float4*>(Bg + (size_t)r * HID + k0 + f * 4);
        }
    };

    loadG(0);
    for (int kc = 0; kc < 32; kc++) {
        #pragma unroll
        for (int i = 0; i < 4; i++) {
            int l = tid + i * 256;
            int r = l >> 3, f = l & 7;
            float4 v = ra[i];
            v.x = tfr(v.x); v.y = tfr(v.y); v.z = tfr(v.z); v.w = tfr(v.w);
            *reinterpret_cast<float4*>(&As[r][f * 4]) = v;
        }
        #pragma unroll
        for (int i = 0; i < 2; i++) {
            int l = tid + i * 256;
            int r = l >> 3, f = l & 7;
            float4 v = rb[i];
            v.x = tfr(v.x); v.y = tfr(v.y); v.z = tfr(v.z); v.w = tfr(v.w);
            *reinterpret_cast<float4*>(&Bs[r][f * 4]) = v;
        }
        __syncthreads();
        if (kc + 1 < 32) loadG(kc + 1);

        #pragma unroll
        for (int kk = 0; kk < 4; kk++) {
            const int k8 = kk * 8;
            unsigned a[2][4], b[4][2];
            #pragma unroll
            for (int mt = 0; mt < 2; mt++) {
                int r0 = wm * 32 + mt * 16 + (lane >> 2);
                a[mt][0] = __float_as_uint(As[r0][k8 + (lane & 3)]);
                a[mt][1] = __float_as_uint(As[r0 + 8][k8 + (lane & 3)]);
                a[mt][2] = __float_as_uint(As[r0][k8 + (lane & 3) + 4]);
                a[mt][3] = __float_as_uint(As[r0 + 8][k8 + (lane & 3) + 4]);
            }
            #pragma unroll
            for (int nt = 0; nt < 4; nt++) {
                int rn = wn * 32 + nt * 8 + (lane >> 2);
                b[nt][0] = __float_as_uint(Bs[rn][k8 + (lane & 3)]);
                b[nt][1] = __float_as_uint(Bs[rn][k8 + (lane & 3) + 4]);
            }
            #pragma unroll
            for (int mt = 0; mt < 2; mt++)
                #pragma unroll
                for (int nt = 0; nt < 4; nt++)
                    mma_tf32(c[mt][nt], a[mt], b[nt]);
        }
        __syncthreads();
    }

    #pragma unroll
    for (int mt = 0; mt < 2; mt++) {
        #pragma unroll
        for (int nt = 0; nt < 4; nt++) {
            int row = m0 + wm * 32 + mt * 16 + (lane >> 2);
            int col = n0 + wn * 32 + nt * 8 + 2 * (lane & 3);
            float b0 = g_b[col], b1 = g_b[col + 1];
            g_gx[(size_t)row * NG + col]           = c[mt][nt][0] + b0;
            g_gx[(size_t)row * NG + col + 1]       = c[mt][nt][1] + b1;
            g_gx[(size_t)(row + 8) * NG + col]     = c[mt][nt][2] + b0;
            g_gx[(size_t)(row + 8) * NG + col + 1] = c[mt][nt][3] + b1;
        }
    }
}

// ============================================================================
// persist_kernel: all 512 recurrent steps in one launch.
// 128 CTAs, 1/SM (150KB smem), all co-resident (single wave) -> spin barrier OK.
// CTA owns h-cols j0..j0+7; W_hh slice (32 rows x 1024) lives in SMEM (tf32).
// Per step: stream h through double-buffered SMEM, MMA vs resident W,
// fused gate/cell epilogue, grid barrier.
// ============================================================================
__global__ __launch_bounds__(256) void persist_kernel() {
    extern __shared__ float sm[];
    float* Ws = sm;                         // [32][WSTR]
    float* AsB = sm + 32 * WSTR;            // 2 x [64][36]
    float* sg  = AsB;                       // epilogue scratch aliases As buf0

    const int tid = threadIdx.x, wid = tid >> 5, lane = tid & 31;
    const int wn = wid & 3;                 // gate
    const int wm = wid >> 2;                // 0..1
    const int j0 = blockIdx.x * 8;

    // ---- prologue: W_hh slice -> SMEM (tf32) ----
    // 32 rows x 1024 cols = 8192 float4 loads over 256 threads
    for (int i = tid; i < 32 * 256; i += 256) {
        int r = i >> 8, f = i & 255;        // r: W row idx, f: float4 idx
        int gate = r >> 3, jj = r & 7;
        // g_wsum trick not needed: plain W_hh (passed via g_wsum? no — use global W_hh copy)
        // W_hh base passed through g_wsum? We need raw W_hh: stored in g_wsum minus W_ih.
        // Instead: read from the const pointer captured below.
        (void)gate; (void)jj; (void)f; (void)r;
        break; // replaced below (see loop with Whh pointer)
    }
    // (actual fill happens in the templated body below)
    // -- to keep pointer plumbing simple, W_hh is passed as a kernel arg --
    // (see real signature: this placeholder removed)
    // NOTE: this block intentionally unreachable; real fill below.
    // ---------------------------------------------------------------

    // This kernel is compiled only through the wrapper below.
    (void)Ws; (void)AsB; (void)sg; (void)wn; (void)wm; (void)j0; (void)lane; (void)wid;
}

// Real persistent kernel (takes W_hh pointer).
__global__ __launch_bounds__(256) void persist2_kernel(const float* __restrict__ Whh) {
    extern __shared__ float sm[];
    float* Ws  = sm;                        // [32][WSTR]
    float* AsB = sm + 32 * WSTR;            // 2 x [64*36]
    float* sg  = AsB;                       // epilogue scratch (aliases As buf0)

    const int tid = threadIdx.x, wid = tid >> 5, lane = tid & 31;
    const int wn = wid & 3;                 // gate index
    const int wm = wid >> 2;                // 0..1
    const int j0 = blockIdx.x * 8;

    // ---- prologue: load this CTA's W_hh slice into SMEM, tf32-converted ----
    for (int i = tid; i < 32 * 256; i += 256) {
        int r = i >> 8, f = i & 255;        // r: 0..31 local row, f: 0..255 float4
        int gate = r >> 3, jj = r & 7;
        float4 v = *reinterpret_cast<const float4*>(
            Whh + (size_t)(gate * HID + j0 + jj) * HID + f * 4);
        v.x = tfr(v.x); v.y = tfr(v.y); v.z = tfr(v.z); v.w = tfr(v.w);
        *reinterpret_cast<float4*>(&Ws[r * WSTR + f * 4]) = v;
    }
    __syncthreads();

    const int arow0 = wm * 32 + (lane >> 2);      // fragment row base
    const int jjc   = 2 * (lane & 3);             // fragment col base (within 8)
    const int rn    = wn * 8 + (lane >> 2);       // Ws row for b-frag

    for (int t = 0; t < S_LEN; t++) {
        const float* __restrict__ h_in  = g_h[t & 1];
        float*       __restrict__ h_out = g_h[(t + 1) & 1];
        const float* __restrict__ gx_t  = g_gx + (size_t)t * BATCH * NG;

        // prefetch gx (input projection + bias) — consumed in epilogue
        float gxr[2][4];
        #pragma unroll
        for (int mt = 0; mt < 2; mt++) {
            int row = arow0 + mt * 16;
            int n   = wn * HID + j0 + jjc;
            gxr[mt][0] = gx_t[(size_t)row * NG + n];
            gxr[mt][1] = gx_t[(size_t)row * NG + n + 1];
            gxr[mt][2] = gx_t[(size_t)(row + 8) * NG + n];
            gxr[mt][3] = gx_t[(size_t)(row + 8) * NG + n + 1];
        }

        float c[2][4];
        #pragma unroll
        for (int mt = 0; mt < 2; mt++)
            #pragma unroll
            for (int r = 0; r < 4; r++) c[mt][r] = 0.f;

        // ---- k-loop: stream h through double-buffered As ----
        float4 ra[2];
        auto loadH = [&](int kc) {
            const int k0 = kc * 32;
            #pragma unroll
            for (int i = 0; i < 2; i++) {
                int l = tid + i * 256;
                int r = l >> 3, f = l & 7;
                ra[i] = *reinterpret_cast<const float4*>(h_in + (size_t)r * HID + k0 + f * 4);
            }
        };
        auto storeH = [&](int buf) {
            #pragma unroll
            for (int i = 0; i < 2; i++) {
                int l = tid + i * 256;
                int r = l >> 3, f = l & 7;
                float4 v = ra[i];
                v.x = tfr(v.x); v.y = tfr(v.y); v.z = tfr(v.z); v.w = tfr(v.w);
                *reinterpret_cast<float4*>(&AsB[buf * (64 * 36) + r * 36 + f * 4]) = v;
            }
        };

        loadH(0);
        storeH(0);
        __syncthreads();

        for (int kc = 0; kc < 32; kc++) {
            if (kc + 1 < 32) loadH(kc + 1);
            const float* As = AsB + (kc & 1) * (64 * 36);

            #pragma unroll
            for (int kk = 0; kk < 4; kk++) {
                const int k8 = kk * 8;
                const int kglob = kc * 32 + k8;
                unsigned a[2][4], b[2];
                #pragma unroll
                for (int mt = 0; mt < 2; mt++) {
                    int r0 = arow0 + mt * 16;
                    a[mt][0] = __float_as_uint(As[r0 * 36 + k8 + (lane & 3)]);
                    a[mt][1] = __float_as_uint(As[(r0 + 8) * 36 + k8 + (lane & 3)]);
                    a[mt][2] = __float_as_uint(As[r0 * 36 + k8 + (lane & 3) + 4]);
                    a[mt][3] = __float_as_uint(As[(r0 + 8) * 36 + k8 + (lane & 3) + 4]);
                }
                b[0] = __float_as_uint(Ws[rn * WSTR + kglob + (lane & 3)]);
                b[1] = __float_as_uint(Ws[rn * WSTR + kglob + (lane & 3) + 4]);
                #pragma unroll
                for (int mt = 0; mt < 2; mt++)
                    mma_tf32(c[mt], a[mt], b);
            }
            if (kc + 1 < 32) {
                __syncthreads();            // all warps done with buf (kc+1)&1
                storeH((kc + 1) & 1);
                __syncthreads();
            }
        }
        // NOTE: last chunk (kc=31) computed from buf1; sg aliases buf0 — safe.

        // ---- gate exchange via SMEM ----
        #pragma unroll
        for (int mt = 0; mt < 2; mt++) {
            int row = arow0 + mt * 16;
            sg[(wn * 64 + row) * 9 + jjc]         = c[mt][0] + gxr[mt][0];
            sg[(wn * 64 + row) * 9 + jjc + 1]     = c[mt][1] + gxr[mt][1];
            sg[(wn * 64 + row + 8) * 9 + jjc]     = c[mt][2] + gxr[mt][2];
            sg[(wn * 64 + row + 8) * 9 + jjc + 1] = c[mt][3] + gxr[mt][3];
        }
        __syncthreads();

        // ---- elementwise cell update for 64x8 slice ----
        for (int q = tid; q < BATCH * 8; q += 256) {
            int m = q >> 3, jj = q & 7;
            float gi = sg[(0 * 64 + m) * 9 + jj];
            float gf = sg[(1 * 64 + m) * 9 + jj];
            float gg = sg[(2 * 64 + m) * 9 + jj];
            float go = sg[(3 * 64 + m) * 9 + jj];
            int cidx = m * HID + j0 + jj;
            float cold = g_c[cidx];
            float si = 1.f / (1.f + expf(-gi));
            float sf = 1.f / (1.f + expf(-gf));
            float so = 1.f / (1.f + expf(-go));
            float cn = sf * cold + si * tanhf(gg);
            float hn = so * tanhf(cn);
            g_c[cidx]   = cn;
            h_out[cidx] = hn;
        }

        // ---- grid barrier (monotonic counter; reset by prep each replay) ----
        __syncthreads();
        if (tid == 0) {
            __threadfence();
            atomicAdd(&g_bar, 1u);
            unsigned target = (unsigned)(t + 1) * GRID;
            while (*(volatile unsigned*)&g_bar < target) { }
            __threadfence();
        }
        __syncthreads();
    }
}

// ============================================================================
// step_kernel<true>: autoregressive steps (gates = g_b + h @ Wsum^T)
// ============================================================================
__global__ __launch_bounds__(256) void ar_step_kernel(int t, float* __restrict__ out_slot) {
    __shared__ float sm[64 * 36 + 32 * 36];
    float (*As)[36] = reinterpret_cast<float(*)[36]>(sm);
    float (*Bs)[36] = reinterpret_cast<float(*)[36]>(sm + 64 * 36);

    const int tid = threadIdx.x, wid = tid >> 5, lane = tid & 31;
    const int wn = wid & 3;
    const int wm = wid >> 2;
    const int j0 = blockIdx.x * 8;

    const float* __restrict__ h_in  = g_h[t & 1];
    float*       __restrict__ h_out = g_h[(t + 1) & 1];
    const float* __restrict__ W     = g_wsum;

    float c[2][4];
    #pragma unroll
    for (int mt = 0; mt < 2; mt++) {
        int jj = 2 * (lane & 3);
        int n  = wn * HID + j0 + jj;
        float b0 = g_b[n], b1 = g_b[n + 1];
        c[mt][0] = b0; c[mt][1] = b1;
        c[mt][2] = b0; c[mt][3] = b1;
    }

    float4 ra[2], rb;
    auto loadG = [&](int kc) {
        const int k0 = kc * 32;
        #pragma unroll
        for (int i = 0; i < 2; i++) {
            int l = tid + i * 256;
            int r = l >> 3, f = l & 7;
            ra[i] = *reinterpret_cast<const float4*>(h_in + (size_t)r * HID + k0 + f * 4);
        }
        {
            int r = tid >> 3, f = tid & 7;
            int gate = r >> 3, jj2 = r & 7;
            rb = *reinterpret_cast<const float4*>(
                W + (size_t)(gate * HID + j0 + jj2) * HID + k0 + f * 4);
        }
    };

    loadG(0);
    for (int kc = 0; kc < 32; kc++) {
        #pragma unroll
        for (int i = 0; i < 2; i++) {
            int l = tid + i * 256;
            int r = l >> 3, f = l & 7;
            float4 va = ra[i];
            va.x = tfr(va.x); va.y = tfr(va.y); va.z = tfr(va.z); va.w = tfr(va.w);
            *reinterpret_cast<float4*>(&As[r][f * 4]) = va;
        }
        {
            int r = tid >> 3, f = tid & 7;
            float4 vb = rb;
            vb.x = tfr(vb.x); vb.y = tfr(vb.y); vb.z = tfr(vb.z); vb.w = tfr(vb.w);
            *reinterpret_cast<float4*>(&Bs[r][f * 4]) = vb;
        }
        __syncthreads();
        if (kc + 1 < 32) loadG(kc + 1);

        #pragma unroll
        for (int kk = 0; kk < 4; kk++) {
            const int k8 = kk * 8;
            unsigned a[2][4], b[2];
            #pragma unroll
            for (int mt = 0; mt < 2; mt++) {
                int r0 = wm * 32 + mt * 16 + (lane >> 2);
                a[mt][0] = __float_as_uint(As[r0][k8 + (lane & 3)]);
                a[mt][1] = __float_as_uint(As[r0 + 8][k8 + (lane & 3)]);
                a[mt][2] = __float_as_uint(As[r0][k8 + (lane & 3) + 4]);
                a[mt][3] = __float_as_uint(As[r0 + 8][k8 + (lane & 3) + 4]);
            }
            {
                int rn = wn * 8 + (lane >> 2);
                b[0] = __float_as_uint(Bs[rn][k8 + (lane & 3)]);
                b[1] = __float_as_uint(Bs[rn][k8 + (lane & 3) + 4]);
            }
            #pragma unroll
            for (int mt = 0; mt < 2; mt++)
                mma_tf32(c[mt], a[mt], b);
        }
        __syncthreads();
    }

    float* sg = sm;
    #pragma unroll
    for (int mt = 0; mt < 2; mt++) {
        int row = wm * 32 + mt * 16 + (lane >> 2);
        int jj  = 2 * (lane & 3);
        sg[(wn * 64 + row) * 9 + jj]         = c[mt][0];
        sg[(wn * 64 + row) * 9 + jj + 1]     = c[mt][1];
        sg[(wn * 64 + row + 8) * 9 + jj]     = c[mt][2];
        sg[(wn * 64 + row + 8) * 9 + jj + 1] = c[mt][3];
    }
    __syncthreads();

    for (int q = tid; q < BATCH * 8; q += 256) {
        int m = q >> 3, jj = q & 7;
        float gi = sg[(0 * 64 + m) * 9 + jj];
        float gf = sg[(1 * 64 + m) * 9 + jj];
        float gg = sg[(2 * 64 + m) * 9 + jj];
        float go = sg[(3 * 64 + m) * 9 + jj];
        int cidx = m * HID + j0 + jj;
        float cold = g_c[cidx];
        float si = 1.f / (1.f + expf(-gi));
        float sf = 1.f / (1.f + expf(-gf));
        float so = 1.f / (1.f + expf(-go));
        float cn = sf * cold + si * tanhf(gg);
        float hn = so * tanhf(cn);
        g_c[cidx]   = cn;
        h_out[cidx] = hn;
        out_slot[cidx] = hn;
    }
}

// ============================================================================
// launch
// ============================================================================
extern "C" void kernel_launch(void* const* d_in, const int* in_sizes, int n_in,
                              void* d_out, int out_size) {
    (void)in_sizes; (void)n_in; (void)out_size;
    const float* x    = (const float*)d_in[0];
    const float* hx0  = (const float*)d_in[1];
    const float* cx0  = (const float*)d_in[2];
    const float* W_ih = (const float*)d_in[3];
    const float* W_hh = (const float*)d_in[4];
    const float* b_ih = (const float*)d_in[5];
    const float* b_hh = (const float*)d_in[6];
    float* out = (float*)d_out;

    static bool attr_set = false;
    const int PERSIST_SMEM = (32 * WSTR + 2 * 64 * 36) * 4;  // ~150 KB
    if (!attr_set) {
        cudaFuncSetAttribute(persist2_kernel,
                             cudaFuncAttributeMaxDynamicSharedMemorySize, PERSIST_SMEM);
        attr_set = true;
    }

    // 1. prep: biases, Wsum, state init, barrier reset
    prep_kernel<<<(NG * HID + 255) / 256, 256>>>(W_ih, W_hh, b_ih, b_hh, hx0, cx0);

    // 2. precompute input projections for all 512 steps
    dim3 gA(NG / 64, MTOT / 128);
    gemmA_kernel<<<gA, 256>>>(x, W_ih);

    // 3. all 512 recurrent steps in one persistent launch
    persist2_kernel<<<GRID, 256, PERSIST_SMEM>>>(W_hh);

    // 4. two autoregressive steps; write h to output
    for (int t = S_LEN; t < S_LEN + 2; t++)
        ar_step_kernel<<<HID / 8, 256>>>(t, out + (size_t)(t - S_LEN) * BATCH * HID);
}